// round 16
// baseline (speedup 1.0000x reference)
#include <cuda_runtime.h>
#include <math.h>

#define NBOX 256

// Level tiling: block = (batch, PIXB pixels) x all C channels.
// threads = GR pixel-groups (float4) x CT channel-slices; PC = C/CT = 8
// float4 pairs (256B) per thread for every level.
#define NB0 1600   // 16 * (6400/64)
#define NB1 800    // 16 * (1600/32)
#define NB2 400    // 16 * (400/16)
#define NB_TOT (NB0 + NB1 + NB2)   // 2800

// Scalar accumulators (zero at load; epilogue restores zero each replay)
__device__ double g_sse[3];
__device__ double g_summ[3];
__device__ int    g_done;

// ---------------------------------------------------------------------------
// dual block reduction over 256 threads (shared buf passed in: 16 floats)
__device__ __forceinline__ void block_reduce_sum2(float& a, float& b, float* sh) {
    #pragma unroll
    for (int off = 16; off > 0; off >>= 1) {
        a += __shfl_down_sync(0xffffffffu, a, off);
        b += __shfl_down_sync(0xffffffffu, b, off);
    }
    int lane = threadIdx.x & 31;
    int wid  = threadIdx.x >> 5;
    if (lane == 0) { sh[wid] = a; sh[8 + wid] = b; }
    __syncthreads();
    if (wid == 0) {
        a = (lane < 8) ? sh[lane] : 0.0f;
        b = (lane < 8) ? sh[8 + lane] : 0.0f;
        #pragma unroll
        for (int off = 4; off > 0; off >>= 1) {
            a += __shfl_down_sync(0xffffffffu, a, off);
            b += __shfl_down_sync(0xffffffffu, b, off);
        }
    }
}

// ---------------------------------------------------------------------------
// Per-level body. Streams all C channels of PIXB pixels, reduces per-pixel
// channel sums via smem, computes the CenterNet gaussian mask inline (once
// per pixel globally; denom STD^2*(w/2)^2 = w^2 for STD=2, exp(-(tx+ty))),
// then sse += m^2 * acc, summ += m (exact: sum_c (m*(p-t))^2 = m^2*sum_c).
template<int C, int S, int PIXB, int LEVEL>
__device__ __forceinline__ void body(const float4* __restrict__ p,
                                     const float4* __restrict__ t,
                                     int blkl,
                                     const float* __restrict__ bboxes,
                                     const int* __restrict__ bidx,
                                     float* s_part, float4* s_box,
                                     int* s_cnt, float* s_red) {
    constexpr int GR     = PIXB / 4;
    constexpr int CT     = 256 / GR;
    constexpr int PC     = C / CT;          // 8 for all levels
    static_assert(PC == 8, "PC must be 8");
    constexpr int PLANE4 = S * S / 4;
    constexpr int PER_IM = (S * S) / PIXB;

    int tid   = threadIdx.x;
    int b     = blkl / PER_IM;
    int chunk = blkl - b * PER_IM;
    int g     = tid % GR;                   // pixel-group (fastest -> coalesced)
    int ct    = tid / GR;                   // channel slice
    int j     = chunk * GR + g;
    int base  = (b * C + ct * PC) * PLANE4 + j;

    if (tid == 0) *s_cnt = 0;
    __syncthreads();
    // filter this batch's boxes into smem (order irrelevant: max commutes)
    if (bidx[tid] == b) {
        int slot = atomicAdd(s_cnt, 1);
        s_box[slot] = reinterpret_cast<const float4*>(bboxes)[tid];
    }

    // stream 8 float4 pairs in two batches of 4 (8 LDG.128 in flight)
    float4 pv[4], tv[4];
    #pragma unroll
    for (int u = 0; u < 4; u++) pv[u] = __ldcs(p + base + u * PLANE4);
    #pragma unroll
    for (int u = 0; u < 4; u++) tv[u] = __ldcs(t + base + u * PLANE4);

    float a0 = 0.0f, a1 = 0.0f, a2 = 0.0f, a3 = 0.0f;
    #pragma unroll
    for (int u = 0; u < 4; u++) {
        float d0 = pv[u].x - tv[u].x;
        float d1 = pv[u].y - tv[u].y;
        float d2 = pv[u].z - tv[u].z;
        float d3 = pv[u].w - tv[u].w;
        a0 += d0 * d0; a1 += d1 * d1; a2 += d2 * d2; a3 += d3 * d3;
    }
    base += 4 * PLANE4;
    #pragma unroll
    for (int u = 0; u < 4; u++) pv[u] = __ldcs(p + base + u * PLANE4);
    #pragma unroll
    for (int u = 0; u < 4; u++) tv[u] = __ldcs(t + base + u * PLANE4);
    #pragma unroll
    for (int u = 0; u < 4; u++) {
        float d0 = pv[u].x - tv[u].x;
        float d1 = pv[u].y - tv[u].y;
        float d2 = pv[u].z - tv[u].z;
        float d3 = pv[u].w - tv[u].w;
        a0 += d0 * d0; a1 += d1 * d1; a2 += d2 * d2; a3 += d3 * d3;
    }

    reinterpret_cast<float4*>(s_part)[tid] = make_float4(a0, a1, a2, a3);
    __syncthreads();

    float se = 0.0f, sm = 0.0f;
    if (tid < PIXB) {
        int gg   = tid >> 2;
        int comp = tid & 3;
        // complete channel sum for this pixel
        float acc = 0.0f;
        #pragma unroll 4
        for (int q = 0; q < CT; q++)
            acc += s_part[(q * GR + gg) * 4 + comp];

        // inline gaussian mask for this pixel
        int gp = chunk * PIXB + tid;
        float fy = (float)(gp / S);
        float fx = (float)(gp - (gp / S) * S);
        float fS = (float)S;
        int cnt = *s_cnt;
        float m = 0.0f;
        for (int k = 0; k < cnt; k++) {
            float4 bb = s_box[k];
            float xc = floorf(bb.x * fS);
            float yc = floorf(bb.y * fS);
            float wh = floorf(floorf(bb.z * fS) * 0.5f);
            float hh = floorf(floorf(bb.w * fS) * 0.5f);
            float xl = fmaxf(xc - wh, 0.0f);
            float xr = fminf(xc + wh, fS - 1.0f);
            float yt = fmaxf(yc - hh, 0.0f);
            float yd = fminf(yc + hh, fS - 1.0f);
            float wd = xr - xl + 1.0f;
            float ht = yd - yt + 1.0f;
            float dx = fx - xc, dy = fy - yc;
            float tx = (dx * dx) / (wd * wd);
            float ty = (dy * dy) / (ht * ht);
            bool inb = (fx >= xl) & (fx <= xr) & (fy >= yt) & (fy <= yd);
            float v = inb ? expf(-(tx + ty)) : 0.0f;
            m = fmaxf(m, v);
        }
        se = m * m * acc;
        sm = m;
    }
    block_reduce_sum2(se, sm, s_red);
    if (tid == 0) {
        atomicAdd(&g_sse[LEVEL],  (double)se);
        atomicAdd(&g_summ[LEVEL], (double)sm);
    }
}

// ---------------------------------------------------------------------------
__global__ void __launch_bounds__(256, 4)
fused_kernel(const float4* __restrict__ p0, const float4* __restrict__ t0,
             const float4* __restrict__ p1, const float4* __restrict__ t1,
             const float4* __restrict__ p2, const float4* __restrict__ t2,
             const float* __restrict__ bboxes, const int* __restrict__ bidx,
             float* __restrict__ out) {
    __shared__ float  s_part[256 * 4];   // per-thread float4 partials (4KB)
    __shared__ float4 s_box[NBOX];       // this batch's boxes (worst case 4KB)
    __shared__ int    s_cnt;
    __shared__ float  s_red[16];

    int blk = blockIdx.x;
    if (blk < NB0)
        body<128, 80, 64, 0>(p0, t0, blk,        bboxes, bidx, s_part, s_box, &s_cnt, s_red);
    else if (blk < NB0 + NB1)
        body<256, 40, 32, 1>(p1, t1, blk - NB0,  bboxes, bidx, s_part, s_box, &s_cnt, s_red);
    else
        body<512, 20, 16, 2>(p2, t2, blk - NB0 - NB1, bboxes, bidx, s_part, s_box, &s_cnt, s_red);

    // fused epilogue: last-finishing block computes the loss and restores
    // the accumulators to zero for the next graph replay.
    if (threadIdx.x == 0) {
        __threadfence();
        int v = atomicAdd(&g_done, 1);
        if (v == NB_TOT - 1) {
            volatile double* sse  = g_sse;
            volatile double* summ = g_summ;
            double tot = sse[0] / (128.0 * summ[0])
                       + sse[1] / (256.0 * summ[1])
                       + sse[2] / (512.0 * summ[2]);
            out[0] = (float)(tot / 3.0);
            #pragma unroll
            for (int l = 0; l < 3; l++) { g_sse[l] = 0.0; g_summ[l] = 0.0; }
            g_done = 0;
        }
    }
}

// ---------------------------------------------------------------------------
extern "C" void kernel_launch(void* const* d_in, const int* in_sizes, int n_in,
                              void* d_out, int out_size) {
    // metadata order (interleaved): 0:y_pred0 1:y_true0 2:y_pred1 3:y_true1
    // 4:y_pred2 5:y_true2 6:bboxes 7:cls 8:batch_idx
    const float* p0 = (const float*)d_in[0];
    const float* t0 = (const float*)d_in[1];
    const float* p1 = (const float*)d_in[2];
    const float* t1 = (const float*)d_in[3];
    const float* p2 = (const float*)d_in[4];
    const float* t2 = (const float*)d_in[5];
    const float* bboxes = (const float*)d_in[6];
    const int*   bidx   = (const int*)d_in[8];
    float* out = (float*)d_out;

    fused_kernel<<<NB_TOT, 256>>>((const float4*)p0, (const float4*)t0,
                                  (const float4*)p1, (const float4*)t1,
                                  (const float4*)p2, (const float4*)t2,
                                  bboxes, bidx, out);
}